// round 12
// baseline (speedup 1.0000x reference)
#include <cuda_runtime.h>
#include <cuda_bf16.h>
#include <cstdint>

#define N 4096
#define D 512
#define ITERS 50
#define REG 0.05f
#define INV_REG 20.0f
#define EPS 1e-9f
#define AB (1.0f/4096.0f)

#define BLOCKS_UV 128
#define TPB 512
#define ROWS_PER_BLOCK 32                 // rows per block; 2 per warp

// -------- scratch (device globals: allocation-free contract) --------
__device__ __nv_bfloat16 g_K[(size_t)N * N];        // 32 MB
__device__ __nv_bfloat16 g_KT[(size_t)N * N];       // 32 MB transpose
__device__ __nv_bfloat16 g_Xb[(size_t)N * D];
__device__ __nv_bfloat16 g_Yb[(size_t)N * D];
__device__ float         g_u[N];
__device__ float         g_v[N];
__device__ float         g_Xs[N];
__device__ float         g_Ys[N];
__device__ float         g_lossblk[BLOCKS_UV];
__device__ unsigned      g_bar_count;
__device__ unsigned      g_bar_gen;

// -------- helpers --------
#define SW128(b) ((b) ^ (((b) >> 3) & 0x70))

__device__ __forceinline__ uint32_t smem_u32(const void* p) {
    uint32_t a;
    asm("{ .reg .u64 t; cvta.to.shared.u64 t, %1; cvt.u32.u64 %0, t; }"
        : "=r"(a) : "l"(p));
    return a;
}

__device__ __forceinline__ void ldsm_x4(uint32_t addr, uint32_t& r0, uint32_t& r1,
                                        uint32_t& r2, uint32_t& r3) {
    asm volatile("ldmatrix.sync.aligned.m8n8.x4.shared.b16 {%0,%1,%2,%3}, [%4];"
                 : "=r"(r0), "=r"(r1), "=r"(r2), "=r"(r3) : "r"(addr));
}

__device__ __forceinline__ void mma_16816(float* c, const uint32_t* a,
                                          uint32_t b0, uint32_t b1) {
    asm volatile(
        "mma.sync.aligned.m16n8k16.row.col.f32.bf16.bf16.f32 "
        "{%0,%1,%2,%3}, {%4,%5,%6,%7}, {%8,%9}, {%0,%1,%2,%3};"
        : "+f"(c[0]), "+f"(c[1]), "+f"(c[2]), "+f"(c[3])
        : "r"(a[0]), "r"(a[1]), "r"(a[2]), "r"(a[3]), "r"(b0), "r"(b1));
}

#define CP_ASYNC16(sm, gm) \
    asm volatile("cp.async.cg.shared.global [%0], [%1], 16;" :: "r"(sm), "l"(gm))
#define CP_COMMIT() asm volatile("cp.async.commit_group;" ::: "memory")
#define CP_WAIT1()  asm volatile("cp.async.wait_group 1;" ::: "memory")
#define CP_WAIT0()  asm volatile("cp.async.wait_group 0;" ::: "memory")

#define FMA2(acc, a, b) \
    asm("fma.rn.f32x2 %0, %1, %2, %0;" : "+l"(acc) : "l"(a), "l"(b))

__device__ __forceinline__ unsigned long long bf2_f32x2(unsigned w) {
    unsigned lo = w << 16;
    unsigned hi = w & 0xffff0000u;
    unsigned long long d;
    asm("mov.b64 %0, {%1, %2};" : "=l"(d) : "r"(lo), "r"(hi));
    return d;
}

__device__ __forceinline__ float blockReduceSum(float val) {
    __shared__ float sh[32];
    int lane = threadIdx.x & 31;
    int wid  = threadIdx.x >> 5;
#pragma unroll
    for (int o = 16; o; o >>= 1) val += __shfl_down_sync(0xffffffffu, val, o);
    if (lane == 0) sh[wid] = val;
    __syncthreads();
    int nw = (blockDim.x + 31) >> 5;
    val = (threadIdx.x < nw) ? sh[threadIdx.x] : 0.0f;
    if (wid == 0) {
#pragma unroll
        for (int o = 16; o; o >>= 1) val += __shfl_down_sync(0xffffffffu, val, o);
    }
    return val;
}

// grid barrier, cooperative-groups style
__device__ __forceinline__ void grid_barrier() {
    __syncthreads();
    if (threadIdx.x == 0) {
        unsigned gen;
        asm volatile("ld.acquire.gpu.global.u32 %0, [%1];"
                     : "=r"(gen) : "l"(&g_bar_gen));
        unsigned old;
        asm volatile("atom.release.gpu.global.add.u32 %0, [%1], %2;"
                     : "=r"(old) : "l"(&g_bar_count), "r"(1u));
        if (old == BLOCKS_UV - 1) {
            asm volatile("st.relaxed.gpu.global.u32 [%0], %1;"
                         :: "l"(&g_bar_count), "r"(0u));
            asm volatile("red.release.gpu.global.add.u32 [%0], %1;"
                         :: "l"(&g_bar_gen), "r"(1u));
        } else {
            unsigned cur;
            do {
                asm volatile("ld.acquire.gpu.global.u32 %0, [%1];"
                             : "=r"(cur) : "l"(&g_bar_gen));
            } while (cur == gen);
        }
    }
    __syncthreads();
}

// dual-row dot: rows row0, row0+1 of mat against vsh (f32, shared)
__device__ __forceinline__ void dual_dot(const __nv_bfloat16* mat, int row0,
                                         const float* vsh, int lane,
                                         float& o0, float& o1) {
    const uint4* r0 = (const uint4*)(mat + (size_t)row0 * N);
    const uint4* r1 = (const uint4*)(mat + (size_t)(row0 + 1) * N);
    unsigned long long a0 = 0ULL, a1 = 0ULL;
#pragma unroll 4
    for (int c = 0; c < 16; c++) {
        uint4 k0 = __ldg(&r0[c * 32 + lane]);
        uint4 k1 = __ldg(&r1[c * 32 + lane]);
        const float* vb = vsh + c * 256 + lane * 8;
        uint4 va = *(const uint4*)vb;
        uint4 vc = *(const uint4*)(vb + 4);
        unsigned long long v0 = ((const unsigned long long*)&va)[0];
        unsigned long long v1 = ((const unsigned long long*)&va)[1];
        unsigned long long v2 = ((const unsigned long long*)&vc)[0];
        unsigned long long v3 = ((const unsigned long long*)&vc)[1];
        const unsigned* w0 = (const unsigned*)&k0;
        const unsigned* w1 = (const unsigned*)&k1;
        FMA2(a0, bf2_f32x2(w0[0]), v0);
        FMA2(a0, bf2_f32x2(w0[1]), v1);
        FMA2(a0, bf2_f32x2(w0[2]), v2);
        FMA2(a0, bf2_f32x2(w0[3]), v3);
        FMA2(a1, bf2_f32x2(w1[0]), v0);
        FMA2(a1, bf2_f32x2(w1[1]), v1);
        FMA2(a1, bf2_f32x2(w1[2]), v2);
        FMA2(a1, bf2_f32x2(w1[3]), v3);
    }
    float lo, hi;
    asm("mov.b64 {%0, %1}, %2;" : "=f"(lo), "=f"(hi) : "l"(a0));
    o0 = lo + hi;
    asm("mov.b64 {%0, %1}, %2;" : "=f"(lo), "=f"(hi) : "l"(a1));
    o1 = lo + hi;
}

// -------- kernel 1: norms + bf16 conversion + v<-1 (warp per row) --------
__global__ void __launch_bounds__(256) norms_init_kernel(
    const float* __restrict__ X, const float* __restrict__ Y) {
    int tid  = threadIdx.x;
    int lane = tid & 31;
    int gw   = (blockIdx.x * 256 + tid) >> 5;

    if (blockIdx.x == 0 && tid == 0) g_bar_count = 0;

#pragma unroll
    for (int pass = 0; pass < 2; pass++) {
        int row = gw + pass * 4096;
        bool isX = (row < N);
        int r = isX ? row : row - N;
        const float* src = isX ? (X + (size_t)r * D) : (Y + (size_t)r * D);
        float s = 0.0f;
        uint2 pk[4];
#pragma unroll
        for (int q = 0; q < 4; q++) {
            float4 t = ((const float4*)src)[q * 32 + lane];
            s += t.x * t.x + t.y * t.y + t.z * t.z + t.w * t.w;
            __nv_bfloat162 b0 = __floats2bfloat162_rn(t.x, t.y);
            __nv_bfloat162 b1 = __floats2bfloat162_rn(t.z, t.w);
            pk[q] = make_uint2(*(unsigned*)&b0, *(unsigned*)&b1);
        }
        __nv_bfloat16* dst = isX ? g_Xb : g_Yb;
#pragma unroll
        for (int q = 0; q < 4; q++)
            *(uint2*)(dst + (size_t)r * D + (q * 32 + lane) * 4) = pk[q];
#pragma unroll
        for (int o = 16; o; o >>= 1) s += __shfl_xor_sync(0xffffffffu, s, o);
        if (lane == 0) {
            if (isX) g_Xs[r] = s;
            else     g_Ys[r] = s;
        }
    }
    int gt = blockIdx.x * 256 + tid;
    if (gt < N) g_v[gt] = 1.0f;
}

// -------- kernel 2: bf16 HMMA GEMM, cp.async 2-stage pipeline --------
__global__ void __launch_bounds__(256)
k_gemm_kernel() {
    extern __shared__ __align__(1024) unsigned char dyn[];
    __shared__ float s_ys[128];
    __shared__ float s_xs[128];

    int tid = threadIdx.x;
    int lane = tid & 31, w = tid >> 5;
    int wm = w & 3, wn = w >> 2;
    int bm = blockIdx.y * 128, bn = blockIdx.x * 128;

    if (tid < 128) s_ys[tid] = g_Ys[bn + tid];
    else           s_xs[tid - 128] = g_Xs[bm + tid - 128];

    uint32_t st_base[2];
    st_base[0] = smem_u32(dyn);
    st_base[1] = st_base[0] + 32768;

    float acc[2][8][4];
#pragma unroll
    for (int mt = 0; mt < 2; mt++)
#pragma unroll
        for (int nt = 0; nt < 8; nt++)
#pragma unroll
            for (int q = 0; q < 4; q++) acc[mt][nt][q] = 0.0f;

    int aRow = wm * 32 + (lane & 15);
    int aSeg = (lane >> 4) & 1;
    int bRow = wn * 64 + (lane & 7) + ((lane >> 4) & 1) * 8;
    int bSeg = (lane >> 3) & 1;

    int lrow[4], lsw[4];
#pragma unroll
    for (int i = 0; i < 4; i++) {
        int p = tid + i * 256;
        lrow[i] = p >> 3;
        lsw[i]  = SW128((uint32_t)((p >> 3) * 128 + (p & 7) * 16));
    }

#pragma unroll
    for (int i = 0; i < 4; i++) {
        CP_ASYNC16(st_base[0] + lsw[i],
                   g_Xb + (size_t)(bm + lrow[i]) * D + ((tid + i * 256) & 7) * 8);
        CP_ASYNC16(st_base[0] + 16384 + lsw[i],
                   g_Yb + (size_t)(bn + lrow[i]) * D + ((tid + i * 256) & 7) * 8);
    }
    CP_COMMIT();

    for (int kc = 0; kc < 8; kc++) {
        int st = kc & 1;
        if (kc + 1 < 8) {
            int ns = st ^ 1;
#pragma unroll
            for (int i = 0; i < 4; i++) {
                int c8 = (tid + i * 256) & 7;
                CP_ASYNC16(st_base[ns] + lsw[i],
                           g_Xb + (size_t)(bm + lrow[i]) * D + (kc + 1) * 64 + c8 * 8);
                CP_ASYNC16(st_base[ns] + 16384 + lsw[i],
                           g_Yb + (size_t)(bn + lrow[i]) * D + (kc + 1) * 64 + c8 * 8);
            }
            CP_COMMIT();
            CP_WAIT1();
        } else {
            CP_WAIT0();
        }
        __syncthreads();

        uint32_t sA_base = st_base[st];
        uint32_t sB_base = st_base[st] + 16384;
#pragma unroll
        for (int ks = 0; ks < 4; ks++) {
            uint32_t kbyte = ks * 32;
            uint32_t af[2][4];
#pragma unroll
            for (int mt = 0; mt < 2; mt++) {
                uint32_t byte = (uint32_t)((aRow + mt * 16) * 128) + kbyte + aSeg * 16;
                ldsm_x4(sA_base + SW128(byte), af[mt][0], af[mt][1], af[mt][2], af[mt][3]);
            }
            uint32_t bf[4][4];
#pragma unroll
            for (int np = 0; np < 4; np++) {
                uint32_t byte = (uint32_t)((bRow + np * 16) * 128) + kbyte + bSeg * 16;
                ldsm_x4(sB_base + SW128(byte), bf[np][0], bf[np][1], bf[np][2], bf[np][3]);
            }
#pragma unroll
            for (int mt = 0; mt < 2; mt++)
#pragma unroll
                for (int nt = 0; nt < 8; nt++)
                    mma_16816(acc[mt][nt], af[mt],
                              bf[nt >> 1][(nt & 1) * 2], bf[nt >> 1][(nt & 1) * 2 + 1]);
        }
        __syncthreads();
    }

    int g = lane >> 2, tig = lane & 3;
#pragma unroll
    for (int mt = 0; mt < 2; mt++) {
        int r0l = wm * 32 + mt * 16 + g;
        int r1l = r0l + 8;
        float xs0 = s_xs[r0l], xs1 = s_xs[r1l];
#pragma unroll
        for (int nt = 0; nt < 8; nt++) {
            int cl = wn * 64 + nt * 8 + 2 * tig;
            float ys0 = s_ys[cl], ys1 = s_ys[cl + 1];
            float c00 = fmaxf(xs0 + ys0 - 2.0f * acc[mt][nt][0], 0.0f);
            float c01 = fmaxf(xs0 + ys1 - 2.0f * acc[mt][nt][1], 0.0f);
            float c10 = fmaxf(xs1 + ys0 - 2.0f * acc[mt][nt][2], 0.0f);
            float c11 = fmaxf(xs1 + ys1 - 2.0f * acc[mt][nt][3], 0.0f);
            __nv_bfloat162 k0 = __floats2bfloat162_rn(__expf(-c00 * INV_REG),
                                                      __expf(-c01 * INV_REG));
            __nv_bfloat162 k1 = __floats2bfloat162_rn(__expf(-c10 * INV_REG),
                                                      __expf(-c11 * INV_REG));
            *(__nv_bfloat162*)(g_K + (size_t)(bm + r0l) * N + bn + cl) = k0;
            *(__nv_bfloat162*)(g_K + (size_t)(bm + r1l) * N + bn + cl) = k1;
        }
    }
}

// -------- kernel 3: K -> KT tiled transpose (128x128 bf16 tiles) --------
__global__ void __launch_bounds__(256) transpose_kernel() {
    __shared__ __nv_bfloat16 s[128][136];   // +8 pad
    int bm = blockIdx.y * 128, bn = blockIdx.x * 128;
    int tid = threadIdx.x;
#pragma unroll
    for (int i = 0; i < 8; i++) {
        int p = tid + i * 256;               // 0..2047
        int r = p >> 4, c = p & 15;
        uint4 val = *(const uint4*)(g_K + (size_t)(bm + r) * N + bn + c * 8);
        *(uint4*)&s[r][c * 8] = val;
    }
    __syncthreads();
#pragma unroll
    for (int i = 0; i < 8; i++) {
        int p = tid + i * 256;
        int j = p >> 4, c = p & 15;          // j: KT tile row, c: chunk of 8 cols
        __nv_bfloat16 tmp[8];
#pragma unroll
        for (int q = 0; q < 8; q++) tmp[q] = s[c * 8 + q][j];
        *(uint4*)(g_KT + (size_t)(bn + j) * N + bm + c * 8) = *(uint4*)tmp;
    }
}

// -------- kernel 4: PERSISTENT Sinkhorn, warp-autonomous dual sweeps ----
__global__ void __launch_bounds__(TPB) sinkhorn_kernel(float* __restrict__ out) {
    __shared__ __align__(16) float vec[N];   // 16 KB vector copy
    __shared__ float lacc[ROWS_PER_BLOCK];
    int tid  = threadIdx.x;
    int lane = tid & 31, w = tid >> 5;
    int base = blockIdx.x * ROWS_PER_BLOCK;
    int row0 = base + w * 2;

    for (int it = 0; it < ITERS; ++it) {
        // ---- Phase A: u = a/(K v) ----
        {
            const float4* vg = (const float4*)g_v;
#pragma unroll
            for (int q = 0; q < 2; q++)
                *(float4*)&vec[(tid * 2 + q) * 4] = __ldcg(&vg[tid * 2 + q]);
        }
        __syncthreads();
        {
            float s0, s1;
            dual_dot(g_K, row0, vec, lane, s0, s1);
#pragma unroll
            for (int o = 16; o; o >>= 1) {
                s0 += __shfl_xor_sync(0xffffffffu, s0, o);
                s1 += __shfl_xor_sync(0xffffffffu, s1, o);
            }
            if (lane == 0) {
                g_u[row0]     = AB / (s0 + EPS);
                g_u[row0 + 1] = AB / (s1 + EPS);
            }
        }
        grid_barrier();

        // ---- Phase B: v = b/(K^T u) ----
        {
            const float4* ug = (const float4*)g_u;
#pragma unroll
            for (int q = 0; q < 2; q++)
                *(float4*)&vec[(tid * 2 + q) * 4] = __ldcg(&ug[tid * 2 + q]);
        }
        __syncthreads();
        {
            float s0, s1;
            dual_dot(g_KT, row0, vec, lane, s0, s1);
#pragma unroll
            for (int o = 16; o; o >>= 1) {
                s0 += __shfl_xor_sync(0xffffffffu, s0, o);
                s1 += __shfl_xor_sync(0xffffffffu, s1, o);
            }
            if (lane == 0) {
                g_v[row0]     = AB / (s0 + EPS);
                g_v[row0 + 1] = AB / (s1 + EPS);
            }
        }
        grid_barrier();
    }

    // ---- fused loss: sum_i u_i * sum_j K_ij v_j cost_ij ----
    {
        const float4* vg = (const float4*)g_v;
#pragma unroll
        for (int q = 0; q < 2; q++)
            *(float4*)&vec[(tid * 2 + q) * 4] = __ldcg(&vg[tid * 2 + q]);
    }
    __syncthreads();
    {
        const uint4* r0 = (const uint4*)(g_K + (size_t)row0 * N);
        const uint4* r1 = (const uint4*)(g_K + (size_t)(row0 + 1) * N);
        float s0 = 0.0f, s1 = 0.0f;
        for (int c = 0; c < 16; c++) {
            uint4 k0 = __ldg(&r0[c * 32 + lane]);
            uint4 k1 = __ldg(&r1[c * 32 + lane]);
            const float* vb = vec + c * 256 + lane * 8;
            const __nv_bfloat162* p0 = (const __nv_bfloat162*)&k0;
            const __nv_bfloat162* p1 = (const __nv_bfloat162*)&k1;
#pragma unroll
            for (int q = 0; q < 4; q++) {
                float2 f0 = __bfloat1622float2(p0[q]);
                float2 f1 = __bfloat1622float2(p1[q]);
                float vx = vb[2 * q], vy = vb[2 * q + 1];
                s0 += f0.x * vx * fmaxf(-REG * __logf(f0.x), 0.0f)
                    + f0.y * vy * fmaxf(-REG * __logf(f0.y), 0.0f);
                s1 += f1.x * vx * fmaxf(-REG * __logf(f1.x), 0.0f)
                    + f1.y * vy * fmaxf(-REG * __logf(f1.y), 0.0f);
            }
        }
#pragma unroll
        for (int o = 16; o; o >>= 1) {
            s0 += __shfl_xor_sync(0xffffffffu, s0, o);
            s1 += __shfl_xor_sync(0xffffffffu, s1, o);
        }
        if (lane == 0) {
            lacc[w * 2]     = __ldcg(&g_u[row0]) * s0;
            lacc[w * 2 + 1] = __ldcg(&g_u[row0 + 1]) * s1;
        }
        __syncthreads();
        if (tid == 0) {
            float s = 0.0f;
#pragma unroll
            for (int r = 0; r < ROWS_PER_BLOCK; r++) s += lacc[r];
            g_lossblk[blockIdx.x] = s;
        }
    }

    grid_barrier();

    if (blockIdx.x == 0) {
        float v = (tid < BLOCKS_UV) ? __ldcg(&g_lossblk[tid]) : 0.0f;
        v = blockReduceSum(v);
        if (tid == 0) out[0] = v;
    }
}

// -------- launch --------
extern "C" void kernel_launch(void* const* d_in, const int* in_sizes, int n_in,
                              void* d_out, int out_size) {
    const float* X = (const float*)d_in[0];
    const float* Y = (const float*)d_in[1];
    float* out = (float*)d_out;

    cudaFuncSetAttribute(k_gemm_kernel,
                         cudaFuncAttributeMaxDynamicSharedMemorySize, 65536);

    norms_init_kernel<<<512, 256>>>(X, Y);          // launch 0
    k_gemm_kernel<<<dim3(32, 32), 256, 65536>>>();  // launch 1
    transpose_kernel<<<dim3(32, 32), 256>>>();      // launch 2
    sinkhorn_kernel<<<BLOCKS_UV, TPB>>>(out);       // launch 3 <- ncu target
}

// round 13
// speedup vs baseline: 1.2509x; 1.2509x over previous
#include <cuda_runtime.h>
#include <cuda_bf16.h>
#include <cstdint>

#define N 4096
#define D 512
#define ITERS 50
#define REG 0.05f
#define INV_REG 20.0f
#define EPS 1e-9f
#define AB (1.0f/4096.0f)

#define BLOCKS_UV 128
#define TPB 512
#define ROWS_PER_BLOCK 32                 // 2 rows per warp

// -------- scratch (device globals: allocation-free contract) --------
__device__ __nv_bfloat16 g_K[(size_t)N * N];        // 32 MB
__device__ __nv_bfloat16 g_KT[(size_t)N * N];       // 32 MB transpose
__device__ __nv_bfloat16 g_Xb[(size_t)N * D];
__device__ __nv_bfloat16 g_Yb[(size_t)N * D];
__device__ float         g_u[N];
__device__ float         g_v[N];
__device__ float         g_Xs[N];
__device__ float         g_Ys[N];
__device__ float         g_lossblk[BLOCKS_UV];
__device__ unsigned      g_bar_count;
__device__ unsigned      g_bar_gen;

// -------- helpers --------
#define SW128(b) ((b) ^ (((b) >> 3) & 0x70))

__device__ __forceinline__ uint32_t smem_u32(const void* p) {
    uint32_t a;
    asm("{ .reg .u64 t; cvta.to.shared.u64 t, %1; cvt.u32.u64 %0, t; }"
        : "=r"(a) : "l"(p));
    return a;
}

__device__ __forceinline__ void ldsm_x4(uint32_t addr, uint32_t& r0, uint32_t& r1,
                                        uint32_t& r2, uint32_t& r3) {
    asm volatile("ldmatrix.sync.aligned.m8n8.x4.shared.b16 {%0,%1,%2,%3}, [%4];"
                 : "=r"(r0), "=r"(r1), "=r"(r2), "=r"(r3) : "r"(addr));
}

__device__ __forceinline__ void mma_16816(float* c, const uint32_t* a,
                                          uint32_t b0, uint32_t b1) {
    asm volatile(
        "mma.sync.aligned.m16n8k16.row.col.f32.bf16.bf16.f32 "
        "{%0,%1,%2,%3}, {%4,%5,%6,%7}, {%8,%9}, {%0,%1,%2,%3};"
        : "+f"(c[0]), "+f"(c[1]), "+f"(c[2]), "+f"(c[3])
        : "r"(a[0]), "r"(a[1]), "r"(a[2]), "r"(a[3]), "r"(b0), "r"(b1));
}

#define CP_ASYNC16(sm, gm) \
    asm volatile("cp.async.cg.shared.global [%0], [%1], 16;" :: "r"(sm), "l"(gm))
#define CP_COMMIT() asm volatile("cp.async.commit_group;" ::: "memory")
#define CP_WAIT1()  asm volatile("cp.async.wait_group 1;" ::: "memory")
#define CP_WAIT0()  asm volatile("cp.async.wait_group 0;" ::: "memory")

#define FMA2(acc, a, b) \
    asm("fma.rn.f32x2 %0, %1, %2, %0;" : "+l"(acc) : "l"(a), "l"(b))

__device__ __forceinline__ unsigned long long bf2_f32x2(unsigned w) {
    unsigned lo = w << 16;
    unsigned hi = w & 0xffff0000u;
    unsigned long long d;
    asm("mov.b64 %0, {%1, %2};" : "=l"(d) : "r"(lo), "r"(hi));
    return d;
}

__device__ __forceinline__ float blockReduceSum(float val) {
    __shared__ float sh[32];
    int lane = threadIdx.x & 31;
    int wid  = threadIdx.x >> 5;
#pragma unroll
    for (int o = 16; o; o >>= 1) val += __shfl_down_sync(0xffffffffu, val, o);
    if (lane == 0) sh[wid] = val;
    __syncthreads();
    int nw = (blockDim.x + 31) >> 5;
    val = (threadIdx.x < nw) ? sh[threadIdx.x] : 0.0f;
    if (wid == 0) {
#pragma unroll
        for (int o = 16; o; o >>= 1) val += __shfl_down_sync(0xffffffffu, val, o);
    }
    return val;
}

// grid barrier, cooperative-groups style
__device__ __forceinline__ void grid_barrier() {
    __syncthreads();
    if (threadIdx.x == 0) {
        unsigned gen;
        asm volatile("ld.acquire.gpu.global.u32 %0, [%1];"
                     : "=r"(gen) : "l"(&g_bar_gen));
        unsigned old;
        asm volatile("atom.release.gpu.global.add.u32 %0, [%1], %2;"
                     : "=r"(old) : "l"(&g_bar_count), "r"(1u));
        if (old == BLOCKS_UV - 1) {
            asm volatile("st.relaxed.gpu.global.u32 [%0], %1;"
                         :: "l"(&g_bar_count), "r"(0u));
            asm volatile("red.release.gpu.global.add.u32 [%0], %1;"
                         :: "l"(&g_bar_gen), "r"(1u));
        } else {
            unsigned cur;
            do {
                asm volatile("ld.acquire.gpu.global.u32 %0, [%1];"
                             : "=r"(cur) : "l"(&g_bar_gen));
            } while (cur == gen);
        }
    }
    __syncthreads();
}

// dual-row dot vs bf16 vector in shared (dense LDS.128, deep LDG pipeline)
__device__ __forceinline__ void dual_dot_b(const __nv_bfloat16* mat, int row0,
                                           const __nv_bfloat16* vsh, int lane,
                                           float& o0, float& o1) {
    const uint4* r0 = (const uint4*)(mat + (size_t)row0 * N);
    const uint4* r1 = (const uint4*)(mat + (size_t)(row0 + 1) * N);
    unsigned long long a0 = 0ULL, a1 = 0ULL;
    uint4 b0[2][4], b1[2][4];
#pragma unroll
    for (int c = 0; c < 4; c++) {
        b0[0][c] = __ldg(&r0[c * 32 + lane]);
        b1[0][c] = __ldg(&r1[c * 32 + lane]);
    }
#pragma unroll
    for (int sc = 0; sc < 4; sc++) {
        const int cur = sc & 1, nxt = cur ^ 1;
        if (sc < 3) {
#pragma unroll
            for (int c = 0; c < 4; c++) {
                b0[nxt][c] = __ldg(&r0[((sc + 1) * 4 + c) * 32 + lane]);
                b1[nxt][c] = __ldg(&r1[((sc + 1) * 4 + c) * 32 + lane]);
            }
        }
#pragma unroll
        for (int c = 0; c < 4; c++) {
            int ch = sc * 4 + c;
            uint4 vv = *(const uint4*)(vsh + ch * 256 + lane * 8);  // 8 bf16, dense
            unsigned long long v0 = bf2_f32x2(vv.x);
            unsigned long long v1 = bf2_f32x2(vv.y);
            unsigned long long v2 = bf2_f32x2(vv.z);
            unsigned long long v3 = bf2_f32x2(vv.w);
            const unsigned* w0 = (const unsigned*)&b0[cur][c];
            const unsigned* w1 = (const unsigned*)&b1[cur][c];
            FMA2(a0, bf2_f32x2(w0[0]), v0);
            FMA2(a0, bf2_f32x2(w0[1]), v1);
            FMA2(a0, bf2_f32x2(w0[2]), v2);
            FMA2(a0, bf2_f32x2(w0[3]), v3);
            FMA2(a1, bf2_f32x2(w1[0]), v0);
            FMA2(a1, bf2_f32x2(w1[1]), v1);
            FMA2(a1, bf2_f32x2(w1[2]), v2);
            FMA2(a1, bf2_f32x2(w1[3]), v3);
        }
    }
    float lo, hi;
    asm("mov.b64 {%0, %1}, %2;" : "=f"(lo), "=f"(hi) : "l"(a0));
    o0 = lo + hi;
    asm("mov.b64 {%0, %1}, %2;" : "=f"(lo), "=f"(hi) : "l"(a1));
    o1 = lo + hi;
}

// -------- kernel 1: norms + bf16 conversion + v<-1 (warp per row) --------
__global__ void __launch_bounds__(256) norms_init_kernel(
    const float* __restrict__ X, const float* __restrict__ Y) {
    int tid  = threadIdx.x;
    int lane = tid & 31;
    int gw   = (blockIdx.x * 256 + tid) >> 5;

    if (blockIdx.x == 0 && tid == 0) g_bar_count = 0;

#pragma unroll
    for (int pass = 0; pass < 2; pass++) {
        int row = gw + pass * 4096;
        bool isX = (row < N);
        int r = isX ? row : row - N;
        const float* src = isX ? (X + (size_t)r * D) : (Y + (size_t)r * D);
        float s = 0.0f;
        uint2 pk[4];
#pragma unroll
        for (int q = 0; q < 4; q++) {
            float4 t = ((const float4*)src)[q * 32 + lane];
            s += t.x * t.x + t.y * t.y + t.z * t.z + t.w * t.w;
            __nv_bfloat162 b0 = __floats2bfloat162_rn(t.x, t.y);
            __nv_bfloat162 b1 = __floats2bfloat162_rn(t.z, t.w);
            pk[q] = make_uint2(*(unsigned*)&b0, *(unsigned*)&b1);
        }
        __nv_bfloat16* dst = isX ? g_Xb : g_Yb;
#pragma unroll
        for (int q = 0; q < 4; q++)
            *(uint2*)(dst + (size_t)r * D + (q * 32 + lane) * 4) = pk[q];
#pragma unroll
        for (int o = 16; o; o >>= 1) s += __shfl_xor_sync(0xffffffffu, s, o);
        if (lane == 0) {
            if (isX) g_Xs[r] = s;
            else     g_Ys[r] = s;
        }
    }
    int gt = blockIdx.x * 256 + tid;
    if (gt < N) g_v[gt] = 1.0f;
}

// -------- kernel 2: bf16 HMMA GEMM, cp.async 2-stage pipeline --------
__global__ void __launch_bounds__(256)
k_gemm_kernel() {
    extern __shared__ __align__(1024) unsigned char dyn[];
    __shared__ float s_ys[128];
    __shared__ float s_xs[128];

    int tid = threadIdx.x;
    int lane = tid & 31, w = tid >> 5;
    int wm = w & 3, wn = w >> 2;
    int bm = blockIdx.y * 128, bn = blockIdx.x * 128;

    if (tid < 128) s_ys[tid] = g_Ys[bn + tid];
    else           s_xs[tid - 128] = g_Xs[bm + tid - 128];

    uint32_t st_base[2];
    st_base[0] = smem_u32(dyn);
    st_base[1] = st_base[0] + 32768;

    float acc[2][8][4];
#pragma unroll
    for (int mt = 0; mt < 2; mt++)
#pragma unroll
        for (int nt = 0; nt < 8; nt++)
#pragma unroll
            for (int q = 0; q < 4; q++) acc[mt][nt][q] = 0.0f;

    int aRow = wm * 32 + (lane & 15);
    int aSeg = (lane >> 4) & 1;
    int bRow = wn * 64 + (lane & 7) + ((lane >> 4) & 1) * 8;
    int bSeg = (lane >> 3) & 1;

    int lrow[4], lsw[4];
#pragma unroll
    for (int i = 0; i < 4; i++) {
        int p = tid + i * 256;
        lrow[i] = p >> 3;
        lsw[i]  = SW128((uint32_t)((p >> 3) * 128 + (p & 7) * 16));
    }

#pragma unroll
    for (int i = 0; i < 4; i++) {
        CP_ASYNC16(st_base[0] + lsw[i],
                   g_Xb + (size_t)(bm + lrow[i]) * D + ((tid + i * 256) & 7) * 8);
        CP_ASYNC16(st_base[0] + 16384 + lsw[i],
                   g_Yb + (size_t)(bn + lrow[i]) * D + ((tid + i * 256) & 7) * 8);
    }
    CP_COMMIT();

    for (int kc = 0; kc < 8; kc++) {
        int st = kc & 1;
        if (kc + 1 < 8) {
            int ns = st ^ 1;
#pragma unroll
            for (int i = 0; i < 4; i++) {
                int c8 = (tid + i * 256) & 7;
                CP_ASYNC16(st_base[ns] + lsw[i],
                           g_Xb + (size_t)(bm + lrow[i]) * D + (kc + 1) * 64 + c8 * 8);
                CP_ASYNC16(st_base[ns] + 16384 + lsw[i],
                           g_Yb + (size_t)(bn + lrow[i]) * D + (kc + 1) * 64 + c8 * 8);
            }
            CP_COMMIT();
            CP_WAIT1();
        } else {
            CP_WAIT0();
        }
        __syncthreads();

        uint32_t sA_base = st_base[st];
        uint32_t sB_base = st_base[st] + 16384;
#pragma unroll
        for (int ks = 0; ks < 4; ks++) {
            uint32_t kbyte = ks * 32;
            uint32_t af[2][4];
#pragma unroll
            for (int mt = 0; mt < 2; mt++) {
                uint32_t byte = (uint32_t)((aRow + mt * 16) * 128) + kbyte + aSeg * 16;
                ldsm_x4(sA_base + SW128(byte), af[mt][0], af[mt][1], af[mt][2], af[mt][3]);
            }
            uint32_t bf[4][4];
#pragma unroll
            for (int np = 0; np < 4; np++) {
                uint32_t byte = (uint32_t)((bRow + np * 16) * 128) + kbyte + bSeg * 16;
                ldsm_x4(sB_base + SW128(byte), bf[np][0], bf[np][1], bf[np][2], bf[np][3]);
            }
#pragma unroll
            for (int mt = 0; mt < 2; mt++)
#pragma unroll
                for (int nt = 0; nt < 8; nt++)
                    mma_16816(acc[mt][nt], af[mt],
                              bf[nt >> 1][(nt & 1) * 2], bf[nt >> 1][(nt & 1) * 2 + 1]);
        }
        __syncthreads();
    }

    int g = lane >> 2, tig = lane & 3;
#pragma unroll
    for (int mt = 0; mt < 2; mt++) {
        int r0l = wm * 32 + mt * 16 + g;
        int r1l = r0l + 8;
        float xs0 = s_xs[r0l], xs1 = s_xs[r1l];
#pragma unroll
        for (int nt = 0; nt < 8; nt++) {
            int cl = wn * 64 + nt * 8 + 2 * tig;
            float ys0 = s_ys[cl], ys1 = s_ys[cl + 1];
            float c00 = fmaxf(xs0 + ys0 - 2.0f * acc[mt][nt][0], 0.0f);
            float c01 = fmaxf(xs0 + ys1 - 2.0f * acc[mt][nt][1], 0.0f);
            float c10 = fmaxf(xs1 + ys0 - 2.0f * acc[mt][nt][2], 0.0f);
            float c11 = fmaxf(xs1 + ys1 - 2.0f * acc[mt][nt][3], 0.0f);
            __nv_bfloat162 k0 = __floats2bfloat162_rn(__expf(-c00 * INV_REG),
                                                      __expf(-c01 * INV_REG));
            __nv_bfloat162 k1 = __floats2bfloat162_rn(__expf(-c10 * INV_REG),
                                                      __expf(-c11 * INV_REG));
            *(__nv_bfloat162*)(g_K + (size_t)(bm + r0l) * N + bn + cl) = k0;
            *(__nv_bfloat162*)(g_K + (size_t)(bm + r1l) * N + bn + cl) = k1;
        }
    }
}

// -------- kernel 3: K -> KT tiled transpose --------
__global__ void __launch_bounds__(256) transpose_kernel() {
    __shared__ __nv_bfloat16 s[128][136];
    int bm = blockIdx.y * 128, bn = blockIdx.x * 128;
    int tid = threadIdx.x;
#pragma unroll
    for (int i = 0; i < 8; i++) {
        int p = tid + i * 256;
        int r = p >> 4, c = p & 15;
        uint4 val = *(const uint4*)(g_K + (size_t)(bm + r) * N + bn + c * 8);
        *(uint4*)&s[r][c * 8] = val;
    }
    __syncthreads();
#pragma unroll
    for (int i = 0; i < 8; i++) {
        int p = tid + i * 256;
        int j = p >> 4, c = p & 15;
        __nv_bfloat16 tmp[8];
#pragma unroll
        for (int q = 0; q < 8; q++) tmp[q] = s[c * 8 + q][j];
        *(uint4*)(g_KT + (size_t)(bn + j) * N + bm + c * 8) = *(uint4*)tmp;
    }
}

// -------- kernel 4: PERSISTENT Sinkhorn, bf16 shared vector --------
__global__ void __launch_bounds__(TPB) sinkhorn_kernel(float* __restrict__ out) {
    __shared__ __align__(16) __nv_bfloat16 vecb[N];   // 8 KB bf16 vector
    __shared__ float lacc[ROWS_PER_BLOCK];
    int tid  = threadIdx.x;
    int lane = tid & 31, w = tid >> 5;
    int base = blockIdx.x * ROWS_PER_BLOCK;
    int row0 = base + w * 2;

    for (int it = 0; it < ITERS; ++it) {
        // ---- Phase A: u = a/(K v) ----
        {
            const float4* src = (const float4*)g_v;
#pragma unroll
            for (int q = 0; q < 2; q++) {
                float4 t = __ldcg(&src[tid * 2 + q]);
                __nv_bfloat162 p0 = __floats2bfloat162_rn(t.x, t.y);
                __nv_bfloat162 p1 = __floats2bfloat162_rn(t.z, t.w);
                *(uint2*)&vecb[(tid * 2 + q) * 4] =
                    make_uint2(*(unsigned*)&p0, *(unsigned*)&p1);
            }
        }
        __syncthreads();
        {
            float s0, s1;
            dual_dot_b(g_K, row0, vecb, lane, s0, s1);
#pragma unroll
            for (int o = 16; o; o >>= 1) {
                s0 += __shfl_xor_sync(0xffffffffu, s0, o);
                s1 += __shfl_xor_sync(0xffffffffu, s1, o);
            }
            if (lane == 0) {
                g_u[row0]     = AB / (s0 + EPS);
                g_u[row0 + 1] = AB / (s1 + EPS);
            }
        }
        grid_barrier();

        // ---- Phase B: v = b/(K^T u) ----
        {
            const float4* src = (const float4*)g_u;
#pragma unroll
            for (int q = 0; q < 2; q++) {
                float4 t = __ldcg(&src[tid * 2 + q]);
                __nv_bfloat162 p0 = __floats2bfloat162_rn(t.x, t.y);
                __nv_bfloat162 p1 = __floats2bfloat162_rn(t.z, t.w);
                *(uint2*)&vecb[(tid * 2 + q) * 4] =
                    make_uint2(*(unsigned*)&p0, *(unsigned*)&p1);
            }
        }
        __syncthreads();
        {
            float s0, s1;
            dual_dot_b(g_KT, row0, vecb, lane, s0, s1);
#pragma unroll
            for (int o = 16; o; o >>= 1) {
                s0 += __shfl_xor_sync(0xffffffffu, s0, o);
                s1 += __shfl_xor_sync(0xffffffffu, s1, o);
            }
            if (lane == 0) {
                g_v[row0]     = AB / (s0 + EPS);
                g_v[row0 + 1] = AB / (s1 + EPS);
            }
        }
        grid_barrier();
    }

    // ---- fused loss: sum_i u_i * sum_j K_ij v_j cost_ij ----
    {
        const float4* src = (const float4*)g_v;
#pragma unroll
        for (int q = 0; q < 2; q++) {
            float4 t = __ldcg(&src[tid * 2 + q]);
            __nv_bfloat162 p0 = __floats2bfloat162_rn(t.x, t.y);
            __nv_bfloat162 p1 = __floats2bfloat162_rn(t.z, t.w);
            *(uint2*)&vecb[(tid * 2 + q) * 4] =
                make_uint2(*(unsigned*)&p0, *(unsigned*)&p1);
        }
    }
    __syncthreads();
    {
        const uint4* r0 = (const uint4*)(g_K + (size_t)row0 * N);
        const uint4* r1 = (const uint4*)(g_K + (size_t)(row0 + 1) * N);
        float s0 = 0.0f, s1 = 0.0f;
        for (int c = 0; c < 16; c++) {
            uint4 k0 = __ldg(&r0[c * 32 + lane]);
            uint4 k1 = __ldg(&r1[c * 32 + lane]);
            uint4 vv = *(const uint4*)(vecb + c * 256 + lane * 8);
            const __nv_bfloat162* p0 = (const __nv_bfloat162*)&k0;
            const __nv_bfloat162* p1 = (const __nv_bfloat162*)&k1;
            const __nv_bfloat162* pv = (const __nv_bfloat162*)&vv;
#pragma unroll
            for (int q = 0; q < 4; q++) {
                float2 f0 = __bfloat1622float2(p0[q]);
                float2 f1 = __bfloat1622float2(p1[q]);
                float2 fv = __bfloat1622float2(pv[q]);
                s0 += f0.x * fv.x * fmaxf(-REG * __logf(f0.x), 0.0f)
                    + f0.y * fv.y * fmaxf(-REG * __logf(f0.y), 0.0f);
                s1 += f1.x * fv.x * fmaxf(-REG * __logf(f1.x), 0.0f)
                    + f1.y * fv.y * fmaxf(-REG * __logf(f1.y), 0.0f);
            }
        }
#pragma unroll
        for (int o = 16; o; o >>= 1) {
            s0 += __shfl_xor_sync(0xffffffffu, s0, o);
            s1 += __shfl_xor_sync(0xffffffffu, s1, o);
        }
        if (lane == 0) {
            lacc[w * 2]     = __ldcg(&g_u[row0]) * s0;
            lacc[w * 2 + 1] = __ldcg(&g_u[row0 + 1]) * s1;
        }
        __syncthreads();
        if (tid == 0) {
            float s = 0.0f;
#pragma unroll
            for (int r = 0; r < ROWS_PER_BLOCK; r++) s += lacc[r];
            g_lossblk[blockIdx.x] = s;
        }
    }

    grid_barrier();

    if (blockIdx.x == 0) {
        float v = (tid < BLOCKS_UV) ? __ldcg(&g_lossblk[tid]) : 0.0f;
        v = blockReduceSum(v);
        if (tid == 0) out[0] = v;
    }
}

// -------- launch --------
extern "C" void kernel_launch(void* const* d_in, const int* in_sizes, int n_in,
                              void* d_out, int out_size) {
    const float* X = (const float*)d_in[0];
    const float* Y = (const float*)d_in[1];
    float* out = (float*)d_out;

    cudaFuncSetAttribute(k_gemm_kernel,
                         cudaFuncAttributeMaxDynamicSharedMemorySize, 65536);

    norms_init_kernel<<<512, 256>>>(X, Y);          // launch 0
    k_gemm_kernel<<<dim3(32, 32), 256, 65536>>>();  // launch 1
    transpose_kernel<<<dim3(32, 32), 256>>>();      // launch 2
    sinkhorn_kernel<<<BLOCKS_UV, TPB>>>(out);       // launch 3 <- ncu target
}